// round 1
// baseline (speedup 1.0000x reference)
#include <cuda_runtime.h>

#define Bn 4
#define Tn 2048
#define Cn 1024
#define Hn 16
#define DHn 64
#define SCALE_F 0.125f

// Scratch (allocation-free rule: __device__ globals)
__device__ float g_qkv[Bn * Tn * 3 * Cn];   // [B*T, 3C]  ~100 MB
__device__ float g_attn[Bn * Tn * Cn];      // [B*T, C]   ~33 MB

// ---------------------------------------------------------------------------
// SGEMM (NT): C[m,n] = sum_k A[m,k] * B[n,k]
// A: [M,K] row-major, B: [N,K] row-major (weight), C: [M,N] row-major.
// 128x128x16 tile, 256 threads, 8x8 per thread. M%128==0, N%128==0, K%16==0.
// ---------------------------------------------------------------------------
#define GBM 128
#define GBN 128
#define GBK 16
#define GPAD 132   // padded smem row stride (float4-aligned)

__global__ void __launch_bounds__(256) sgemm_nt(const float* __restrict__ A,
                                                const float* __restrict__ Bw,
                                                float* __restrict__ C,
                                                int M, int N, int K) {
    __shared__ float As[GBK][GPAD];
    __shared__ float Bs[GBK][GPAD];

    const int tid = threadIdx.x;
    const int bm  = blockIdx.y * GBM;
    const int bn  = blockIdx.x * GBN;
    const int tx  = tid & 15;       // 0..15  -> n
    const int ty  = tid >> 4;       // 0..15  -> m

    const int lrow = tid >> 2;          // 0..63
    const int lcol = (tid & 3) << 2;    // 0,4,8,12

    const float* Aptr = A + (long)bm * K;
    const float* Bptr = Bw + (long)bn * K;

    float acc[8][8];
#pragma unroll
    for (int i = 0; i < 8; i++)
#pragma unroll
        for (int j = 0; j < 8; j++) acc[i][j] = 0.f;

    for (int k0 = 0; k0 < K; k0 += GBK) {
#pragma unroll
        for (int half = 0; half < 2; half++) {
            int r = lrow + half * 64;
            float4 va = *(const float4*)(Aptr + (long)r * K + k0 + lcol);
            As[lcol + 0][r] = va.x; As[lcol + 1][r] = va.y;
            As[lcol + 2][r] = va.z; As[lcol + 3][r] = va.w;
            float4 vb = *(const float4*)(Bptr + (long)r * K + k0 + lcol);
            Bs[lcol + 0][r] = vb.x; Bs[lcol + 1][r] = vb.y;
            Bs[lcol + 2][r] = vb.z; Bs[lcol + 3][r] = vb.w;
        }
        __syncthreads();

#pragma unroll
        for (int kk = 0; kk < GBK; kk++) {
            float ra[8], rb[8];
            float4 a0 = *(const float4*)(&As[kk][ty * 8 + 0]);
            float4 a1 = *(const float4*)(&As[kk][ty * 8 + 4]);
            ra[0] = a0.x; ra[1] = a0.y; ra[2] = a0.z; ra[3] = a0.w;
            ra[4] = a1.x; ra[5] = a1.y; ra[6] = a1.z; ra[7] = a1.w;
            float4 b0 = *(const float4*)(&Bs[kk][tx * 8 + 0]);
            float4 b1 = *(const float4*)(&Bs[kk][tx * 8 + 4]);
            rb[0] = b0.x; rb[1] = b0.y; rb[2] = b0.z; rb[3] = b0.w;
            rb[4] = b1.x; rb[5] = b1.y; rb[6] = b1.z; rb[7] = b1.w;
#pragma unroll
            for (int i = 0; i < 8; i++)
#pragma unroll
                for (int j = 0; j < 8; j++)
                    acc[i][j] += ra[i] * rb[j];
        }
        __syncthreads();
    }

#pragma unroll
    for (int i = 0; i < 8; i++) {
        long row = bm + ty * 8 + i;
        float* crow = C + row * N + bn + tx * 8;
        float4 o0 = {acc[i][0], acc[i][1], acc[i][2], acc[i][3]};
        float4 o1 = {acc[i][4], acc[i][5], acc[i][6], acc[i][7]};
        *(float4*)(crow + 0) = o0;
        *(float4*)(crow + 4) = o1;
    }
}

// ---------------------------------------------------------------------------
// Chunked linear attention (no softmax -> exact restructure).
// Per (b,h): carry S[d1][d2] = sum_{s in prior chunks} k_s[d1] * v_s[d2].
// Per chunk (L=64):
//   P[t][s]   = q_t . k_s  (masked s<=t, within chunk)
//   O[t][d]   = SCALE * ( sum_s P[t][s] V[s][d]  +  sum_d1 Q[t][d1] S[d1][d] )
//   S[d1][d2] += sum_t K[t][d1] V[t][d2]
// grid = B*H = 64 blocks, 256 threads, dynamic smem.
// ---------------------------------------------------------------------------
#define LCH 64
#define AST 68   // padded stride, float4-aligned

__global__ void __launch_bounds__(256) attn_linear_kernel(const float* __restrict__ qkv,
                                                          float* __restrict__ out) {
    extern __shared__ float sm[];
    float* Qt = sm;                 // [d][t]
    float* Kt = Qt + LCH * AST;     // [d][s]
    float* Vs = Kt + LCH * AST;     // [s][d]
    float* Ss = Vs + LCH * AST;     // [d1][d2]
    float* Ps = Ss + LCH * AST;     // [s][t], reused as O[t][d]

    const int bh = blockIdx.x;
    const int b = bh / Hn, h = bh % Hn;
    const int tid = threadIdx.x;
    const int tx = tid & 15;        // -> t (P/O) or d2 (S)
    const int ty = tid >> 4;        // -> s (P) / d2 (O) / d1 (S)

    for (int i = tid; i < LCH * AST; i += 256) Ss[i] = 0.f;

    const float* base = qkv + ((long)b * Tn) * (3 * Cn) + h * DHn;
    float* gbase = out + ((long)b * Tn) * Cn + h * DHn;

    for (int c = 0; c < Tn / LCH; c++) {
        const long t0 = (long)c * LCH;
        __syncthreads();   // protect Ss init / prior-iter smem reads

        // ---- load Q,K (transposed) and V (row-major) for this chunk ----
        for (int p = tid; p < LCH * DHn / 4; p += 256) {
            int t = p >> 4;
            int d = (p & 15) << 2;
            const float* rowp = base + (t0 + t) * (3 * Cn);
            float4 q4 = *(const float4*)(rowp + d);
            float4 k4 = *(const float4*)(rowp + Cn + d);
            float4 v4 = *(const float4*)(rowp + 2 * Cn + d);
            Qt[(d + 0) * AST + t] = q4.x; Qt[(d + 1) * AST + t] = q4.y;
            Qt[(d + 2) * AST + t] = q4.z; Qt[(d + 3) * AST + t] = q4.w;
            Kt[(d + 0) * AST + t] = k4.x; Kt[(d + 1) * AST + t] = k4.y;
            Kt[(d + 2) * AST + t] = k4.z; Kt[(d + 3) * AST + t] = k4.w;
            *(float4*)(Vs + t * AST + d) = v4;
        }
        __syncthreads();

        // ---- P[s=ty*4+i][t=tx*4+j] = sum_d K[s][d]*Q[t][d], masked ----
        {
            float pacc[4][4];
#pragma unroll
            for (int i = 0; i < 4; i++)
#pragma unroll
                for (int j = 0; j < 4; j++) pacc[i][j] = 0.f;

            for (int d = 0; d < DHn; d++) {
                float ka[4];
#pragma unroll
                for (int i = 0; i < 4; i++) ka[i] = Kt[d * AST + ty * 4 + i];
                float4 qq = *(const float4*)(Qt + d * AST + tx * 4);
                float qb[4] = {qq.x, qq.y, qq.z, qq.w};
#pragma unroll
                for (int i = 0; i < 4; i++)
#pragma unroll
                    for (int j = 0; j < 4; j++)
                        pacc[i][j] += ka[i] * qb[j];
            }
#pragma unroll
            for (int i = 0; i < 4; i++) {
                int s = ty * 4 + i;
                float4 v;
                v.x = (s <= tx * 4 + 0) ? pacc[i][0] : 0.f;
                v.y = (s <= tx * 4 + 1) ? pacc[i][1] : 0.f;
                v.z = (s <= tx * 4 + 2) ? pacc[i][2] : 0.f;
                v.w = (s <= tx * 4 + 3) ? pacc[i][3] : 0.f;
                *(float4*)(Ps + s * AST + tx * 4) = v;
            }
        }
        __syncthreads();

        // ---- O[t=tx*4+j][d2=ty*4+i] = P@V + Q@S ----
        float oacc[4][4];
#pragma unroll
        for (int i = 0; i < 4; i++)
#pragma unroll
            for (int j = 0; j < 4; j++) oacc[i][j] = 0.f;

        for (int s = 0; s < LCH; s++) {
            float4 pp = *(const float4*)(Ps + s * AST + tx * 4);
            float pj[4] = {pp.x, pp.y, pp.z, pp.w};
            float va[4];
#pragma unroll
            for (int i = 0; i < 4; i++) va[i] = Vs[s * AST + ty * 4 + i];
#pragma unroll
            for (int i = 0; i < 4; i++)
#pragma unroll
                for (int j = 0; j < 4; j++)
                    oacc[i][j] += pj[j] * va[i];
        }
        for (int d1 = 0; d1 < DHn; d1++) {
            float4 qq = *(const float4*)(Qt + d1 * AST + tx * 4);
            float qj[4] = {qq.x, qq.y, qq.z, qq.w};
            float sb[4];
#pragma unroll
            for (int i = 0; i < 4; i++) sb[i] = Ss[d1 * AST + ty * 4 + i];
#pragma unroll
            for (int i = 0; i < 4; i++)
#pragma unroll
                for (int j = 0; j < 4; j++)
                    oacc[i][j] += qj[j] * sb[i];
        }

        // ---- S-update accumulation (reads Kt, Vs only) ----
        float sacc[4][4];
#pragma unroll
        for (int i = 0; i < 4; i++)
#pragma unroll
            for (int j = 0; j < 4; j++) sacc[i][j] = 0.f;

        for (int t = 0; t < LCH; t++) {
            float ka[4];
#pragma unroll
            for (int i = 0; i < 4; i++) ka[i] = Kt[(ty * 4 + i) * AST + t];
            float4 vv = *(const float4*)(Vs + t * AST + tx * 4);
            float vj[4] = {vv.x, vv.y, vv.z, vv.w};
#pragma unroll
            for (int i = 0; i < 4; i++)
#pragma unroll
                for (int j = 0; j < 4; j++)
                    sacc[i][j] += ka[i] * vj[j];
        }

        __syncthreads();   // all reads of Ps / Ss complete

        // commit O into Ps buffer (now O[t][d], row-major over t) and S += sacc
#pragma unroll
        for (int i = 0; i < 4; i++)
#pragma unroll
            for (int j = 0; j < 4; j++)
                Ps[(tx * 4 + j) * AST + ty * 4 + i] = oacc[i][j] * SCALE_F;
#pragma unroll
        for (int i = 0; i < 4; i++) {
            float* srow = Ss + (ty * 4 + i) * AST + tx * 4;
            srow[0] += sacc[i][0]; srow[1] += sacc[i][1];
            srow[2] += sacc[i][2]; srow[3] += sacc[i][3];
        }
        __syncthreads();

        // coalesced global write of O
        for (int p = tid; p < LCH * DHn / 4; p += 256) {
            int t = p >> 4;
            int d = (p & 15) << 2;
            *(float4*)(gbase + (t0 + t) * Cn + d) = *(const float4*)(Ps + t * AST + d);
        }
    }
}

// ---------------------------------------------------------------------------
extern "C" void kernel_launch(void* const* d_in, const int* in_sizes, int n_in,
                              void* d_out, int out_size) {
    const float* x    = (const float*)d_in[0];   // [B,T,C]
    const float* Wqkv = (const float*)d_in[1];   // [3C,C]
    const float* Wout = (const float*)d_in[2];   // [C,C]
    float* out = (float*)d_out;                  // [B,T,C]

    float *qkv_ptr, *attn_ptr;
    cudaGetSymbolAddress((void**)&qkv_ptr, g_qkv);
    cudaGetSymbolAddress((void**)&attn_ptr, g_attn);

    const int M = Bn * Tn;          // 8192
    const int N1 = 3 * Cn;          // 3072
    const int K1 = Cn;              // 1024

    // GEMM1: qkv = x @ Wqkv^T
    {
        dim3 grid(N1 / GBN, M / GBM);
        sgemm_nt<<<grid, 256>>>(x, Wqkv, qkv_ptr, M, N1, K1);
    }

    // Attention (chunked linear, exact)
    {
        const int smem = 5 * LCH * AST * (int)sizeof(float);   // 87,040 B
        cudaFuncSetAttribute(attn_linear_kernel,
                             cudaFuncAttributeMaxDynamicSharedMemorySize, smem);
        attn_linear_kernel<<<Bn * Hn, 256, smem>>>(qkv_ptr, attn_ptr);
    }

    // GEMM2: out = attn @ Wout^T
    {
        dim3 grid(Cn / GBN, M / GBM);
        sgemm_nt<<<grid, 256>>>(attn_ptr, Wout, out, M, Cn, Cn);
    }
}

// round 3
// speedup vs baseline: 2.6688x; 2.6688x over previous
#include <cuda_runtime.h>
#include <cuda_bf16.h>
#include <cstdint>

#define Bn 4
#define Tn 2048
#define Cn 1024
#define Hn 16
#define DHn 64
#define SCALE_F 0.125f
#define KP 3072                 // packed K' = 3*C
#define NCH 32                  // chunks per (b,h)
#define LCH 64                  // chunk length
#define AST 68                  // padded smem stride

// ---------------- scratch (__device__ globals) ------------------------------
__device__ float         g_qkv[Bn * Tn * 3 * Cn];    // [8192,3072] fp32
__device__ float         g_attn[Bn * Tn * Cn];       // [8192,1024] fp32
__device__ __nv_bfloat16 g_xhl[Bn * Tn * KP];
__device__ __nv_bfloat16 g_ahl[Bn * Tn * KP];
__device__ __nv_bfloat16 g_wqkv[3 * Cn * KP];
__device__ __nv_bfloat16 g_wout[Cn * KP];
__device__ float         g_kv[Bn * Hn * NCH * DHn * DHn];  // per-chunk KV sums
__device__ float         g_s [Bn * Hn * NCH * DHn * DHn];  // exclusive prefix

// ---------------- helpers ---------------------------------------------------
__device__ __forceinline__ uint32_t smem_u32(const void* p) {
    uint32_t a;
    asm("{ .reg .u64 t; cvta.to.shared.u64 t, %1; cvt.u32.u64 %0, t; }" : "=r"(a) : "l"(p));
    return a;
}
__device__ __forceinline__ void ldsm_x4(uint32_t& r0, uint32_t& r1, uint32_t& r2,
                                        uint32_t& r3, uint32_t addr) {
    asm volatile("ldmatrix.sync.aligned.m8n8.x4.shared.b16 {%0,%1,%2,%3}, [%4];"
                 : "=r"(r0), "=r"(r1), "=r"(r2), "=r"(r3) : "r"(addr));
}
__device__ __forceinline__ void mma16816(float& d0, float& d1, float& d2, float& d3,
                                         uint32_t a0, uint32_t a1, uint32_t a2, uint32_t a3,
                                         uint32_t b0, uint32_t b1) {
    asm volatile(
        "mma.sync.aligned.m16n8k16.row.col.f32.bf16.bf16.f32 "
        "{%0,%1,%2,%3},{%4,%5,%6,%7},{%8,%9},{%0,%1,%2,%3};"
        : "+f"(d0), "+f"(d1), "+f"(d2), "+f"(d3)
        : "r"(a0), "r"(a1), "r"(a2), "r"(a3), "r"(b0), "r"(b1));
}

// ---------------------------------------------------------------------------
// fp32 -> bf16 hi/lo split-pack. mode 0 (act): [hi|lo|hi]; mode 1 (wt): [hi|hi|lo]
// ---------------------------------------------------------------------------
__global__ void __launch_bounds__(256) cvt_split(const float* __restrict__ in,
                                                 __nv_bfloat16* __restrict__ out,
                                                 int R, int K, int mode) {
    int idx = blockIdx.x * 256 + threadIdx.x;
    int per_row = K >> 2;
    if (idx >= R * per_row) return;
    int r = idx / per_row;
    int k = (idx - r * per_row) << 2;
    float4 v = *(const float4*)(in + (long)r * K + k);

    __nv_bfloat162 h0 = __floats2bfloat162_rn(v.x, v.y);
    __nv_bfloat162 h1 = __floats2bfloat162_rn(v.z, v.w);
    float rx = v.x - __bfloat162float(__low2bfloat16(h0));
    float ry = v.y - __bfloat162float(__high2bfloat16(h0));
    float rz = v.z - __bfloat162float(__low2bfloat16(h1));
    float rw = v.w - __bfloat162float(__high2bfloat16(h1));
    __nv_bfloat162 l0 = __floats2bfloat162_rn(rx, ry);
    __nv_bfloat162 l1 = __floats2bfloat162_rn(rz, rw);

    __nv_bfloat16* o = out + (long)r * (3 * K);
    uint2 hh = {*(uint32_t*)&h0, *(uint32_t*)&h1};
    uint2 ll = {*(uint32_t*)&l0, *(uint32_t*)&l1};
    *(uint2*)(o + k)         = hh;
    *(uint2*)(o + K + k)     = mode ? hh : ll;
    *(uint2*)(o + 2 * K + k) = mode ? ll : hh;
}

// ---------------------------------------------------------------------------
// HMMA bf16 NT GEMM: C[m,n] = sum_k A[m,k]*B[n,k], K = KP fixed.
// CTA 128x128, k-chunk 64 (128B SW128 rows), 3-stage cp.async, 8 warps (32x64).
// ---------------------------------------------------------------------------
#define KC 64
#define NIT (KP / KC)          // 48
#define STG_B 32768            // A 16KB + B 16KB per stage
#define NSTG 3

__global__ void __launch_bounds__(256) gemm_hmma(const __nv_bfloat16* __restrict__ A,
                                                 const __nv_bfloat16* __restrict__ Bw,
                                                 float* __restrict__ C, int N) {
    extern __shared__ __align__(1024) char dsm[];
    const uint32_t smem0 = smem_u32(dsm);

    const int tid = threadIdx.x;
    const int wid = tid >> 5, lid = tid & 31;
    const int bm = blockIdx.y * 128;
    const int bn = blockIdx.x * 128;
    const int wm = (wid & 3) * 32;    // warp M offset
    const int wn = (wid >> 2) * 64;   // warp N offset

    // per-thread cp.async plan: 8 x 16B chunks per stage (2048 chunks total)
    const char* gsrc[8];
    uint32_t sdst[8];
#pragma unroll
    for (int i = 0; i < 8; i++) {
        int c = tid + i * 256;          // 0..2047
        int row = c >> 3;               // 0..255  (0-127 A, 128-255 B)
        int ck = c & 7;
        const __nv_bfloat16* base =
            (row < 128) ? (A + (long)(bm + row) * KP)
                        : (Bw + (long)(bn + row - 128) * KP);
        gsrc[i] = (const char*)base + ck * 16;
        sdst[i] = row * 128 + ((ck ^ (row & 7)) * 16);
    }

    auto load_stage = [&](int j) {
        uint32_t sb = smem0 + (j % NSTG) * STG_B;
        long koff = (long)j * (KC * 2);
#pragma unroll
        for (int i = 0; i < 8; i++) {
            asm volatile("cp.async.cg.shared.global [%0], [%1], 16;"
                         :: "r"(sb + sdst[i]), "l"(gsrc[i] + koff));
        }
        asm volatile("cp.async.commit_group;" ::: "memory");
    };

    float acc[2][8][4];
#pragma unroll
    for (int mt = 0; mt < 2; mt++)
#pragma unroll
        for (int nt = 0; nt < 8; nt++)
#pragma unroll
            for (int q = 0; q < 4; q++) acc[mt][nt][q] = 0.f;

    load_stage(0);
    load_stage(1);

    // ldmatrix lane roles
    const int mat = lid >> 3, r8 = lid & 7;
    // A: row = wm + mt*16 + (mat&1)*8 + r8 ; khalf = mat>>1
    // B: row = 128 + wn + nb*16 + (mat>>1)*8 + r8 ; khalf = mat&1
    const int arow = wm + (mat & 1) * 8 + r8;
    const int brow = 128 + wn + (mat >> 1) * 8 + r8;
    const int akh = mat >> 1;
    const int bkh = mat & 1;

    for (int it = 0; it < NIT; it++) {
        asm volatile("cp.async.wait_group 1;" ::: "memory");
        __syncthreads();

        uint32_t sb = smem0 + (it % NSTG) * STG_B;
#pragma unroll
        for (int ks = 0; ks < 4; ks++) {
            uint32_t af[2][4], bf[4][4];
#pragma unroll
            for (int mt = 0; mt < 2; mt++) {
                int row = arow + mt * 16;
                int ck = (ks * 2 + akh) ^ (row & 7);
                ldsm_x4(af[mt][0], af[mt][1], af[mt][2], af[mt][3],
                        sb + row * 128 + ck * 16);
            }
#pragma unroll
            for (int nb = 0; nb < 4; nb++) {
                int row = brow + nb * 16;
                int ck = (ks * 2 + bkh) ^ (row & 7);
                ldsm_x4(bf[nb][0], bf[nb][1], bf[nb][2], bf[nb][3],
                        sb + row * 128 + ck * 16);
            }
#pragma unroll
            for (int mt = 0; mt < 2; mt++)
#pragma unroll
                for (int nt = 0; nt < 8; nt++) {
                    uint32_t b0 = bf[nt >> 1][(nt & 1) * 2 + 0];
                    uint32_t b1 = bf[nt >> 1][(nt & 1) * 2 + 1];
                    mma16816(acc[mt][nt][0], acc[mt][nt][1],
                             acc[mt][nt][2], acc[mt][nt][3],
                             af[mt][0], af[mt][1], af[mt][2], af[mt][3], b0, b1);
                }
        }
        __syncthreads();
        if (it + 2 < NIT) load_stage(it + 2);
    }

    // epilogue: direct fp32 stores
    const int erow = lid >> 2;          // 0..7
    const int ecol = (lid & 3) * 2;     // 0,2,4,6
#pragma unroll
    for (int mt = 0; mt < 2; mt++) {
#pragma unroll
        for (int nt = 0; nt < 8; nt++) {
            long r0 = bm + wm + mt * 16 + erow;
            long col = bn + wn + nt * 8 + ecol;
            float2 v0 = {acc[mt][nt][0], acc[mt][nt][1]};
            float2 v1 = {acc[mt][nt][2], acc[mt][nt][3]};
            *(float2*)(C + r0 * N + col)       = v0;
            *(float2*)(C + (r0 + 8) * N + col) = v1;
        }
    }
}

// ---------------------------------------------------------------------------
// Attention stage A: per-chunk KV_c[d1][d2] = sum_t K[t][d1]*V[t][d2]
// grid (NCH, B*H), 256 threads.
// ---------------------------------------------------------------------------
__global__ void __launch_bounds__(256) chunk_kv_kernel(const float* __restrict__ qkv,
                                                       float* __restrict__ kv) {
    __shared__ float Kt[DHn * AST];   // [d1][t]
    __shared__ float Vs[LCH * AST];   // [t][d2]

    const int c = blockIdx.x, bh = blockIdx.y;
    const int b = bh / Hn, h = bh % Hn;
    const int tid = threadIdx.x;
    const int tx = tid & 15, ty = tid >> 4;
    const long t0 = (long)c * LCH;

    const float* base = qkv + ((long)b * Tn) * (3 * Cn) + h * DHn;
    for (int p = tid; p < LCH * DHn / 4; p += 256) {
        int t = p >> 4;
        int d = (p & 15) << 2;
        const float* rowp = base + (t0 + t) * (3 * Cn);
        float4 k4 = *(const float4*)(rowp + Cn + d);
        float4 v4 = *(const float4*)(rowp + 2 * Cn + d);
        Kt[(d + 0) * AST + t] = k4.x; Kt[(d + 1) * AST + t] = k4.y;
        Kt[(d + 2) * AST + t] = k4.z; Kt[(d + 3) * AST + t] = k4.w;
        *(float4*)(Vs + t * AST + d) = v4;
    }
    __syncthreads();

    float sacc[4][4];
#pragma unroll
    for (int i = 0; i < 4; i++)
#pragma unroll
        for (int j = 0; j < 4; j++) sacc[i][j] = 0.f;

    for (int t = 0; t < LCH; t++) {
        float ka[4];
#pragma unroll
        for (int i = 0; i < 4; i++) ka[i] = Kt[(ty * 4 + i) * AST + t];
        float4 vv = *(const float4*)(Vs + t * AST + tx * 4);
        float vj[4] = {vv.x, vv.y, vv.z, vv.w};
#pragma unroll
        for (int i = 0; i < 4; i++)
#pragma unroll
            for (int j = 0; j < 4; j++)
                sacc[i][j] += ka[i] * vj[j];
    }

    float* outp = kv + ((long)(bh * NCH + c) << 12);
#pragma unroll
    for (int i = 0; i < 4; i++) {
        float4 v = {sacc[i][0], sacc[i][1], sacc[i][2], sacc[i][3]};
        *(float4*)(outp + (ty * 4 + i) * DHn + tx * 4) = v;
    }
}

// ---------------------------------------------------------------------------
// Attention stage B: exclusive prefix of KV over chunks. grid B*H.
// ---------------------------------------------------------------------------
__global__ void __launch_bounds__(256) prefix_kernel(const float* __restrict__ kv,
                                                     float* __restrict__ s) {
    const int bh = blockIdx.x;
    const int tid = threadIdx.x;
    float S[16];
#pragma unroll
    for (int i = 0; i < 16; i++) S[i] = 0.f;

    for (int c = 0; c < NCH; c++) {
        long base = (long)(bh * NCH + c) << 12;
#pragma unroll
        for (int i = 0; i < 16; i++) {
            s[base + tid + i * 256] = S[i];
            S[i] += kv[base + tid + i * 256];
        }
    }
}

// ---------------------------------------------------------------------------
// Attention stage C: per-chunk output. grid (NCH, B*H).
// O = SCALE * ( mask(Q K^T) V + Q S_prev )
// ---------------------------------------------------------------------------
__global__ void __launch_bounds__(256) attn_out_kernel(const float* __restrict__ qkv,
                                                       const float* __restrict__ s,
                                                       float* __restrict__ out) {
    extern __shared__ float sm[];
    float* Qt = sm;                 // [d][t]
    float* Kt = Qt + DHn * AST;     // [d][s]
    float* Vs = Kt + DHn * AST;     // [s][d]
    float* Ss = Vs + LCH * AST;     // [d1][d2]
    float* Ps = Ss + DHn * AST;     // [s][t] -> O[t][d]

    const int c = blockIdx.x, bh = blockIdx.y;
    const int b = bh / Hn, h = bh % Hn;
    const int tid = threadIdx.x;
    const int tx = tid & 15, ty = tid >> 4;
    const long t0 = (long)c * LCH;

    const float* base = qkv + ((long)b * Tn) * (3 * Cn) + h * DHn;
    const float* sbase = s + ((long)(bh * NCH + c) << 12);

    for (int p = tid; p < LCH * DHn / 4; p += 256) {
        int t = p >> 4;
        int d = (p & 15) << 2;
        const float* rowp = base + (t0 + t) * (3 * Cn);
        float4 q4 = *(const float4*)(rowp + d);
        float4 k4 = *(const float4*)(rowp + Cn + d);
        float4 v4 = *(const float4*)(rowp + 2 * Cn + d);
        Qt[(d + 0) * AST + t] = q4.x; Qt[(d + 1) * AST + t] = q4.y;
        Qt[(d + 2) * AST + t] = q4.z; Qt[(d + 3) * AST + t] = q4.w;
        Kt[(d + 0) * AST + t] = k4.x; Kt[(d + 1) * AST + t] = k4.y;
        Kt[(d + 2) * AST + t] = k4.z; Kt[(d + 3) * AST + t] = k4.w;
        *(float4*)(Vs + t * AST + d) = v4;
        // Ss load: same index space (64*64/4 = 1024 float4s)
        int d1 = p >> 4;
        int d2 = (p & 15) << 2;
        *(float4*)(Ss + d1 * AST + d2) = *(const float4*)(sbase + d1 * DHn + d2);
    }
    __syncthreads();

    // P[s][t] = K[s].Q[t], causal mask s<=t
    {
        float pacc[4][4];
#pragma unroll
        for (int i = 0; i < 4; i++)
#pragma unroll
            for (int j = 0; j < 4; j++) pacc[i][j] = 0.f;

        for (int d = 0; d < DHn; d++) {
            float ka[4];
#pragma unroll
            for (int i = 0; i < 4; i++) ka[i] = Kt[d * AST + ty * 4 + i];
            float4 qq = *(const float4*)(Qt + d * AST + tx * 4);
            float qb[4] = {qq.x, qq.y, qq.z, qq.w};
#pragma unroll
            for (int i = 0; i < 4; i++)
#pragma unroll
                for (int j = 0; j < 4; j++)
                    pacc[i][j] += ka[i] * qb[j];
        }
#pragma unroll
        for (int i = 0; i < 4; i++) {
            int sIdx = ty * 4 + i;
            float4 v;
            v.x = (sIdx <= tx * 4 + 0) ? pacc[i][0] : 0.f;
            v.y = (sIdx <= tx * 4 + 1) ? pacc[i][1] : 0.f;
            v.z = (sIdx <= tx * 4 + 2) ? pacc[i][2] : 0.f;
            v.w = (sIdx <= tx * 4 + 3) ? pacc[i][3] : 0.f;
            *(float4*)(Ps + sIdx * AST + tx * 4) = v;
        }
    }
    __syncthreads();

    // O[t][d2] = P@V + Q@S
    float oacc[4][4];
#pragma unroll
    for (int i = 0; i < 4; i++)
#pragma unroll
        for (int j = 0; j < 4; j++) oacc[i][j] = 0.f;

    for (int sIdx = 0; sIdx < LCH; sIdx++) {
        float4 pp = *(const float4*)(Ps + sIdx * AST + tx * 4);
        float pj[4] = {pp.x, pp.y, pp.z, pp.w};
        float va[4];
#pragma unroll
        for (int i = 0; i < 4; i++) va[i] = Vs[sIdx * AST + ty * 4 + i];
#pragma unroll
        for (int i = 0; i < 4; i++)
#pragma unroll
            for (int j = 0; j < 4; j++)
                oacc[i][j] += pj[j] * va[i];
    }
    for (int d1 = 0; d1 < DHn; d1++) {
        float4 qq = *(const float4*)(Qt + d1 * AST + tx * 4);
        float qj[4] = {qq.x, qq.y, qq.z, qq.w};
        float sb[4];
#pragma unroll
        for (int i = 0; i < 4; i++) sb[i] = Ss[d1 * AST + ty * 4 + i];
#pragma unroll
        for (int i = 0; i < 4; i++)
#pragma unroll
            for (int j = 0; j < 4; j++)
                oacc[i][j] += qj[j] * sb[i];
    }
    __syncthreads();

#pragma unroll
    for (int i = 0; i < 4; i++)
#pragma unroll
        for (int j = 0; j < 4; j++)
            Ps[(tx * 4 + j) * AST + ty * 4 + i] = oacc[i][j] * SCALE_F;
    __syncthreads();

    float* gbase = out + ((long)b * Tn) * Cn + h * DHn;
    for (int p = tid; p < LCH * DHn / 4; p += 256) {
        int t = p >> 4;
        int d = (p & 15) << 2;
        *(float4*)(gbase + (t0 + t) * Cn + d) = *(const float4*)(Ps + t * AST + d);
    }
}

// ---------------------------------------------------------------------------
extern "C" void kernel_launch(void* const* d_in, const int* in_sizes, int n_in,
                              void* d_out, int out_size) {
    const float* x    = (const float*)d_in[0];
    const float* Wqkv = (const float*)d_in[1];
    const float* Wout = (const float*)d_in[2];
    float* out = (float*)d_out;

    float *qkv_p, *attn_p, *kv_p, *s_p;
    __nv_bfloat16 *xhl_p, *ahl_p, *wq_p, *wo_p;
    cudaGetSymbolAddress((void**)&qkv_p, g_qkv);
    cudaGetSymbolAddress((void**)&attn_p, g_attn);
    cudaGetSymbolAddress((void**)&kv_p, g_kv);
    cudaGetSymbolAddress((void**)&s_p, g_s);
    cudaGetSymbolAddress((void**)&xhl_p, g_xhl);
    cudaGetSymbolAddress((void**)&ahl_p, g_ahl);
    cudaGetSymbolAddress((void**)&wq_p, g_wqkv);
    cudaGetSymbolAddress((void**)&wo_p, g_wout);

    const int M = Bn * Tn;                       // 8192
    const int gemm_smem = NSTG * STG_B;          // 98304
    cudaFuncSetAttribute(gemm_hmma, cudaFuncAttributeMaxDynamicSharedMemorySize, gemm_smem);

    // converts
    cvt_split<<<(M * Cn / 4 + 255) / 256, 256>>>(x, xhl_p, M, Cn, 0);
    cvt_split<<<(3 * Cn * Cn / 4 + 255) / 256, 256>>>(Wqkv, wq_p, 3 * Cn, Cn, 1);
    cvt_split<<<(Cn * Cn / 4 + 255) / 256, 256>>>(Wout, wo_p, Cn, Cn, 1);

    // GEMM1: qkv = x @ Wqkv^T
    {
        dim3 grid(3 * Cn / 128, M / 128);
        gemm_hmma<<<grid, 256, gemm_smem>>>(xhl_p, wq_p, qkv_p, 3 * Cn);
    }

    // attention: chunk KV -> prefix -> per-chunk output
    {
        dim3 gkv(NCH, Bn * Hn);
        chunk_kv_kernel<<<gkv, 256>>>(qkv_p, kv_p);
        prefix_kernel<<<Bn * Hn, 256>>>(kv_p, s_p);
        const int asmem = (3 * DHn + 2 * LCH) * AST * (int)sizeof(float);  // 87,040
        cudaFuncSetAttribute(attn_out_kernel,
                             cudaFuncAttributeMaxDynamicSharedMemorySize, asmem);
        attn_out_kernel<<<gkv, 256, asmem>>>(qkv_p, s_p, attn_p);
    }

    // convert attention output + GEMM2
    cvt_split<<<(M * Cn / 4 + 255) / 256, 256>>>(attn_p, ahl_p, M, Cn, 0);
    {
        dim3 grid(Cn / 128, M / 128);
        gemm_hmma<<<grid, 256, gemm_smem>>>(ahl_p, wo_p, out, Cn);
    }
}

// round 4
// speedup vs baseline: 2.8677x; 1.0745x over previous
#include <cuda_runtime.h>
#include <cuda_bf16.h>
#include <cstdint>

#define Bn 4
#define Tn 2048
#define Cn 1024
#define Hn 16
#define DHn 64
#define SCALE_F 0.125f
#define KP 3072                 // packed K' = 3*C
#define NCH 32                  // chunks per (b,h)
#define LCH 64                  // chunk length
#define AST 68                  // padded smem stride

// ---------------- scratch (__device__ globals) ------------------------------
__device__ float         g_qkv[Bn * Tn * 3 * Cn];    // [8192,3072] fp32
__device__ __nv_bfloat16 g_xhl[Bn * Tn * KP];
__device__ __nv_bfloat16 g_ahl[Bn * Tn * KP];
__device__ __nv_bfloat16 g_wqkv[3 * Cn * KP];
__device__ __nv_bfloat16 g_wout[Cn * KP];
__device__ float         g_kv[Bn * Hn * NCH * DHn * DHn];
__device__ float         g_s [Bn * Hn * NCH * DHn * DHn];

// ---------------- helpers ---------------------------------------------------
__device__ __forceinline__ uint32_t smem_u32(const void* p) {
    uint32_t a;
    asm("{ .reg .u64 t; cvta.to.shared.u64 t, %1; cvt.u32.u64 %0, t; }" : "=r"(a) : "l"(p));
    return a;
}
__device__ __forceinline__ void ldsm_x4(uint32_t& r0, uint32_t& r1, uint32_t& r2,
                                        uint32_t& r3, uint32_t addr) {
    asm volatile("ldmatrix.sync.aligned.m8n8.x4.shared.b16 {%0,%1,%2,%3}, [%4];"
                 : "=r"(r0), "=r"(r1), "=r"(r2), "=r"(r3) : "r"(addr));
}
__device__ __forceinline__ void mma16816(float& d0, float& d1, float& d2, float& d3,
                                         uint32_t a0, uint32_t a1, uint32_t a2, uint32_t a3,
                                         uint32_t b0, uint32_t b1) {
    asm volatile(
        "mma.sync.aligned.m16n8k16.row.col.f32.bf16.bf16.f32 "
        "{%0,%1,%2,%3},{%4,%5,%6,%7},{%8,%9},{%0,%1,%2,%3};"
        : "+f"(d0), "+f"(d1), "+f"(d2), "+f"(d3)
        : "r"(a0), "r"(a1), "r"(a2), "r"(a3), "r"(b0), "r"(b1));
}

// split one float4 into hi/lo bf16x4 pairs (packed as uint2)
__device__ __forceinline__ void split4(float4 v, uint2& hh, uint2& ll) {
    __nv_bfloat162 h0 = __floats2bfloat162_rn(v.x, v.y);
    __nv_bfloat162 h1 = __floats2bfloat162_rn(v.z, v.w);
    float rx = v.x - __bfloat162float(__low2bfloat16(h0));
    float ry = v.y - __bfloat162float(__high2bfloat16(h0));
    float rz = v.z - __bfloat162float(__low2bfloat16(h1));
    float rw = v.w - __bfloat162float(__high2bfloat16(h1));
    __nv_bfloat162 l0 = __floats2bfloat162_rn(rx, ry);
    __nv_bfloat162 l1 = __floats2bfloat162_rn(rz, rw);
    hh.x = *(uint32_t*)&h0; hh.y = *(uint32_t*)&h1;
    ll.x = *(uint32_t*)&l0; ll.y = *(uint32_t*)&l1;
}

// ---------------------------------------------------------------------------
// fp32 -> bf16 hi/lo split-pack. mode 0 (act): [hi|lo|hi]; mode 1 (wt): [hi|hi|lo]
// ---------------------------------------------------------------------------
__global__ void __launch_bounds__(256) cvt_split(const float* __restrict__ in,
                                                 __nv_bfloat16* __restrict__ out,
                                                 int R, int K, int mode) {
    int idx = blockIdx.x * 256 + threadIdx.x;
    int per_row = K >> 2;
    if (idx >= R * per_row) return;
    int r = idx / per_row;
    int k = (idx - r * per_row) << 2;
    float4 v = *(const float4*)(in + (long)r * K + k);
    uint2 hh, ll;
    split4(v, hh, ll);
    __nv_bfloat16* o = out + (long)r * (3 * K);
    *(uint2*)(o + k)         = hh;
    *(uint2*)(o + K + k)     = mode ? hh : ll;
    *(uint2*)(o + 2 * K + k) = mode ? ll : hh;
}

// ---------------------------------------------------------------------------
// HMMA bf16 NT GEMM: C[m,n] = sum_k A[m,k]*B[n,k], K = KP fixed.
// CTA 128x128, k-chunk 64, 3-stage cp.async, 8 warps (32x64), 2 CTAs/SM.
// ---------------------------------------------------------------------------
#define KC 64
#define NIT (KP / KC)          // 48
#define STG_B 32768            // A 16KB + B 16KB per stage
#define NSTG 3

__global__ void __launch_bounds__(256, 2) gemm_hmma(const __nv_bfloat16* __restrict__ A,
                                                    const __nv_bfloat16* __restrict__ Bw,
                                                    float* __restrict__ C, int N) {
    extern __shared__ __align__(1024) char dsm[];
    const uint32_t smem0 = smem_u32(dsm);

    const int tid = threadIdx.x;
    const int wid = tid >> 5, lid = tid & 31;
    const int bm = blockIdx.y * 128;
    const int bn = blockIdx.x * 128;
    const int wm = (wid & 3) * 32;
    const int wn = (wid >> 2) * 64;

    // per-thread cp.async plan: 8 x 16B chunks per stage
    const char* gsrc[8];
    uint32_t sdst[8];
#pragma unroll
    for (int i = 0; i < 8; i++) {
        int c = tid + i * 256;
        int row = c >> 3;
        int ck = c & 7;
        const __nv_bfloat16* base =
            (row < 128) ? (A + (long)(bm + row) * KP)
                        : (Bw + (long)(bn + row - 128) * KP);
        gsrc[i] = (const char*)base + ck * 16;
        sdst[i] = row * 128 + ((ck ^ (row & 7)) * 16);
    }

    auto load_stage = [&](int j) {
        uint32_t sb = smem0 + (j % NSTG) * STG_B;
        long koff = (long)j * (KC * 2);
#pragma unroll
        for (int i = 0; i < 8; i++) {
            asm volatile("cp.async.cg.shared.global [%0], [%1], 16;"
                         :: "r"(sb + sdst[i]), "l"(gsrc[i] + koff));
        }
        asm volatile("cp.async.commit_group;" ::: "memory");
    };

    float acc[2][8][4];
#pragma unroll
    for (int mt = 0; mt < 2; mt++)
#pragma unroll
        for (int nt = 0; nt < 8; nt++)
#pragma unroll
            for (int q = 0; q < 4; q++) acc[mt][nt][q] = 0.f;

    load_stage(0);
    load_stage(1);

    const int mat = lid >> 3, r8 = lid & 7;
    const int arow = wm + (mat & 1) * 8 + r8;
    const int brow = 128 + wn + (mat >> 1) * 8 + r8;
    const int akh = mat >> 1;
    const int bkh = mat & 1;

    for (int it = 0; it < NIT; it++) {
        if (it + 1 < NIT) {
            asm volatile("cp.async.wait_group 1;" ::: "memory");
        } else {
            asm volatile("cp.async.wait_group 0;" ::: "memory");
        }
        __syncthreads();
        // safe: stage (it+2)%3 == (it-1)%3, fully consumed before this barrier
        if (it + 2 < NIT) load_stage(it + 2);

        uint32_t sb = smem0 + (it % NSTG) * STG_B;
#pragma unroll
        for (int ks = 0; ks < 4; ks++) {
            uint32_t af[2][4], bf[4][4];
#pragma unroll
            for (int mt = 0; mt < 2; mt++) {
                int row = arow + mt * 16;
                int ck = (ks * 2 + akh) ^ (row & 7);
                ldsm_x4(af[mt][0], af[mt][1], af[mt][2], af[mt][3],
                        sb + row * 128 + ck * 16);
            }
#pragma unroll
            for (int nb = 0; nb < 4; nb++) {
                int row = brow + nb * 16;
                int ck = (ks * 2 + bkh) ^ (row & 7);
                ldsm_x4(bf[nb][0], bf[nb][1], bf[nb][2], bf[nb][3],
                        sb + row * 128 + ck * 16);
            }
#pragma unroll
            for (int mt = 0; mt < 2; mt++)
#pragma unroll
                for (int nt = 0; nt < 8; nt++) {
                    uint32_t b0 = bf[nt >> 1][(nt & 1) * 2 + 0];
                    uint32_t b1 = bf[nt >> 1][(nt & 1) * 2 + 1];
                    mma16816(acc[mt][nt][0], acc[mt][nt][1],
                             acc[mt][nt][2], acc[mt][nt][3],
                             af[mt][0], af[mt][1], af[mt][2], af[mt][3], b0, b1);
                }
        }
    }

    const int erow = lid >> 2;
    const int ecol = (lid & 3) * 2;
#pragma unroll
    for (int mt = 0; mt < 2; mt++) {
#pragma unroll
        for (int nt = 0; nt < 8; nt++) {
            long r0 = bm + wm + mt * 16 + erow;
            long col = bn + wn + nt * 8 + ecol;
            float2 v0 = {acc[mt][nt][0], acc[mt][nt][1]};
            float2 v1 = {acc[mt][nt][2], acc[mt][nt][3]};
            *(float2*)(C + r0 * N + col)       = v0;
            *(float2*)(C + (r0 + 8) * N + col) = v1;
        }
    }
}

// ---------------------------------------------------------------------------
// Attention stage A: per-chunk KV_c[d1][d2] = sum_t K[t][d1]*V[t][d2]
// ---------------------------------------------------------------------------
__global__ void __launch_bounds__(256) chunk_kv_kernel(const float* __restrict__ qkv,
                                                       float* __restrict__ kv) {
    __shared__ float Kt[DHn * AST];
    __shared__ float Vs[LCH * AST];

    const int c = blockIdx.x, bh = blockIdx.y;
    const int b = bh / Hn, h = bh % Hn;
    const int tid = threadIdx.x;
    const int tx = tid & 15, ty = tid >> 4;
    const long t0 = (long)c * LCH;

    const float* base = qkv + ((long)b * Tn) * (3 * Cn) + h * DHn;
    for (int p = tid; p < LCH * DHn / 4; p += 256) {
        int t = p >> 4;
        int d = (p & 15) << 2;
        const float* rowp = base + (t0 + t) * (3 * Cn);
        float4 k4 = *(const float4*)(rowp + Cn + d);
        float4 v4 = *(const float4*)(rowp + 2 * Cn + d);
        Kt[(d + 0) * AST + t] = k4.x; Kt[(d + 1) * AST + t] = k4.y;
        Kt[(d + 2) * AST + t] = k4.z; Kt[(d + 3) * AST + t] = k4.w;
        *(float4*)(Vs + t * AST + d) = v4;
    }
    __syncthreads();

    float sacc[4][4];
#pragma unroll
    for (int i = 0; i < 4; i++)
#pragma unroll
        for (int j = 0; j < 4; j++) sacc[i][j] = 0.f;

    for (int t = 0; t < LCH; t++) {
        float ka[4];
#pragma unroll
        for (int i = 0; i < 4; i++) ka[i] = Kt[(ty * 4 + i) * AST + t];
        float4 vv = *(const float4*)(Vs + t * AST + tx * 4);
        float vj[4] = {vv.x, vv.y, vv.z, vv.w};
#pragma unroll
        for (int i = 0; i < 4; i++)
#pragma unroll
            for (int j = 0; j < 4; j++)
                sacc[i][j] += ka[i] * vj[j];
    }

    float* outp = kv + ((long)(bh * NCH + c) << 12);
#pragma unroll
    for (int i = 0; i < 4; i++) {
        float4 v = {sacc[i][0], sacc[i][1], sacc[i][2], sacc[i][3]};
        *(float4*)(outp + (ty * 4 + i) * DHn + tx * 4) = v;
    }
}

// ---------------------------------------------------------------------------
// Attention stage B: exclusive prefix over chunks. grid (B*H, 16).
// ---------------------------------------------------------------------------
__global__ void __launch_bounds__(256) prefix_kernel(const float* __restrict__ kv,
                                                     float* __restrict__ s) {
    const int bh = blockIdx.x;
    const int idx = blockIdx.y * 256 + threadIdx.x;   // 0..4095
    float S = 0.f;
#pragma unroll 4
    for (int c = 0; c < NCH; c++) {
        long base = (long)(bh * NCH + c) << 12;
        s[base + idx] = S;
        S += kv[base + idx];
    }
}

// ---------------------------------------------------------------------------
// Attention stage C: per-chunk output, fused bf16 hi/lo split epilogue.
// O = SCALE * ( mask(Q K^T) V + Q S_prev )  ->  g_ahl rows [hi|lo|hi]
// ---------------------------------------------------------------------------
__global__ void __launch_bounds__(256) attn_out_kernel(const float* __restrict__ qkv,
                                                       const float* __restrict__ s,
                                                       __nv_bfloat16* __restrict__ ahl) {
    extern __shared__ float sm[];
    float* Qt = sm;                 // [d][t]
    float* Kt = Qt + DHn * AST;     // [d][s]
    float* Vs = Kt + DHn * AST;     // [s][d]
    float* Ss = Vs + LCH * AST;     // [d1][d2]
    float* Ps = Ss + DHn * AST;     // [s][t] -> O[t][d]

    const int c = blockIdx.x, bh = blockIdx.y;
    const int b = bh / Hn, h = bh % Hn;
    const int tid = threadIdx.x;
    const int tx = tid & 15, ty = tid >> 4;
    const long t0 = (long)c * LCH;

    const float* base = qkv + ((long)b * Tn) * (3 * Cn) + h * DHn;
    const float* sbase = s + ((long)(bh * NCH + c) << 12);

    for (int p = tid; p < LCH * DHn / 4; p += 256) {
        int t = p >> 4;
        int d = (p & 15) << 2;
        const float* rowp = base + (t0 + t) * (3 * Cn);
        float4 q4 = *(const float4*)(rowp + d);
        float4 k4 = *(const float4*)(rowp + Cn + d);
        float4 v4 = *(const float4*)(rowp + 2 * Cn + d);
        Qt[(d + 0) * AST + t] = q4.x; Qt[(d + 1) * AST + t] = q4.y;
        Qt[(d + 2) * AST + t] = q4.z; Qt[(d + 3) * AST + t] = q4.w;
        Kt[(d + 0) * AST + t] = k4.x; Kt[(d + 1) * AST + t] = k4.y;
        Kt[(d + 2) * AST + t] = k4.z; Kt[(d + 3) * AST + t] = k4.w;
        *(float4*)(Vs + t * AST + d) = v4;
        *(float4*)(Ss + t * AST + d) = *(const float4*)(sbase + t * DHn + d);
    }
    __syncthreads();

    // P[s][t] = K[s].Q[t], causal mask s<=t
    {
        float pacc[4][4];
#pragma unroll
        for (int i = 0; i < 4; i++)
#pragma unroll
            for (int j = 0; j < 4; j++) pacc[i][j] = 0.f;

        for (int d = 0; d < DHn; d++) {
            float ka[4];
#pragma unroll
            for (int i = 0; i < 4; i++) ka[i] = Kt[d * AST + ty * 4 + i];
            float4 qq = *(const float4*)(Qt + d * AST + tx * 4);
            float qb[4] = {qq.x, qq.y, qq.z, qq.w};
#pragma unroll
            for (int i = 0; i < 4; i++)
#pragma unroll
                for (int j = 0; j < 4; j++)
                    pacc[i][j] += ka[i] * qb[j];
        }
#pragma unroll
        for (int i = 0; i < 4; i++) {
            int sIdx = ty * 4 + i;
            float4 v;
            v.x = (sIdx <= tx * 4 + 0) ? pacc[i][0] : 0.f;
            v.y = (sIdx <= tx * 4 + 1) ? pacc[i][1] : 0.f;
            v.z = (sIdx <= tx * 4 + 2) ? pacc[i][2] : 0.f;
            v.w = (sIdx <= tx * 4 + 3) ? pacc[i][3] : 0.f;
            *(float4*)(Ps + sIdx * AST + tx * 4) = v;
        }
    }
    __syncthreads();

    float oacc[4][4];
#pragma unroll
    for (int i = 0; i < 4; i++)
#pragma unroll
        for (int j = 0; j < 4; j++) oacc[i][j] = 0.f;

    for (int sIdx = 0; sIdx < LCH; sIdx++) {
        float4 pp = *(const float4*)(Ps + sIdx * AST + tx * 4);
        float pj[4] = {pp.x, pp.y, pp.z, pp.w};
        float va[4];
#pragma unroll
        for (int i = 0; i < 4; i++) va[i] = Vs[sIdx * AST + ty * 4 + i];
#pragma unroll
        for (int i = 0; i < 4; i++)
#pragma unroll
            for (int j = 0; j < 4; j++)
                oacc[i][j] += pj[j] * va[i];
    }
    for (int d1 = 0; d1 < DHn; d1++) {
        float4 qq = *(const float4*)(Qt + d1 * AST + tx * 4);
        float qj[4] = {qq.x, qq.y, qq.z, qq.w};
        float sb[4];
#pragma unroll
        for (int i = 0; i < 4; i++) sb[i] = Ss[d1 * AST + ty * 4 + i];
#pragma unroll
        for (int i = 0; i < 4; i++)
#pragma unroll
            for (int j = 0; j < 4; j++)
                oacc[i][j] += qj[j] * sb[i];
    }
    __syncthreads();

#pragma unroll
    for (int i = 0; i < 4; i++)
#pragma unroll
        for (int j = 0; j < 4; j++)
            Ps[(tx * 4 + j) * AST + ty * 4 + i] = oacc[i][j] * SCALE_F;
    __syncthreads();

    // fused hi/lo split writeback: row layout [hi | lo | hi] into g_ahl
    __nv_bfloat16* abase = ahl + ((long)b * Tn + t0) * KP + h * DHn;
    for (int p = tid; p < LCH * DHn / 4; p += 256) {
        int t = p >> 4;
        int d = (p & 15) << 2;
        float4 v = *(const float4*)(Ps + t * AST + d);
        uint2 hh, ll;
        split4(v, hh, ll);
        __nv_bfloat16* o = abase + (long)t * KP;
        *(uint2*)(o + d)          = hh;
        *(uint2*)(o + Cn + d)     = ll;
        *(uint2*)(o + 2 * Cn + d) = hh;
    }
}

// ---------------------------------------------------------------------------
extern "C" void kernel_launch(void* const* d_in, const int* in_sizes, int n_in,
                              void* d_out, int out_size) {
    const float* x    = (const float*)d_in[0];
    const float* Wqkv = (const float*)d_in[1];
    const float* Wout = (const float*)d_in[2];
    float* out = (float*)d_out;

    float *qkv_p, *kv_p, *s_p;
    __nv_bfloat16 *xhl_p, *ahl_p, *wq_p, *wo_p;
    cudaGetSymbolAddress((void**)&qkv_p, g_qkv);
    cudaGetSymbolAddress((void**)&kv_p, g_kv);
    cudaGetSymbolAddress((void**)&s_p, g_s);
    cudaGetSymbolAddress((void**)&xhl_p, g_xhl);
    cudaGetSymbolAddress((void**)&ahl_p, g_ahl);
    cudaGetSymbolAddress((void**)&wq_p, g_wqkv);
    cudaGetSymbolAddress((void**)&wo_p, g_wout);

    const int M = Bn * Tn;                       // 8192
    const int gemm_smem = NSTG * STG_B;          // 98304
    cudaFuncSetAttribute(gemm_hmma, cudaFuncAttributeMaxDynamicSharedMemorySize, gemm_smem);

    // converts
    cvt_split<<<(M * Cn / 4 + 255) / 256, 256>>>(x, xhl_p, M, Cn, 0);
    cvt_split<<<(3 * Cn * Cn / 4 + 255) / 256, 256>>>(Wqkv, wq_p, 3 * Cn, Cn, 1);
    cvt_split<<<(Cn * Cn / 4 + 255) / 256, 256>>>(Wout, wo_p, Cn, Cn, 1);

    // GEMM1: qkv = x @ Wqkv^T
    {
        dim3 grid(3 * Cn / 128, M / 128);
        gemm_hmma<<<grid, 256, gemm_smem>>>(xhl_p, wq_p, qkv_p, 3 * Cn);
    }

    // attention: chunk KV -> prefix -> per-chunk output (+ fused bf16 split)
    {
        dim3 gkv(NCH, Bn * Hn);
        chunk_kv_kernel<<<gkv, 256>>>(qkv_p, kv_p);
        dim3 gpre(Bn * Hn, 16);
        prefix_kernel<<<gpre, 256>>>(kv_p, s_p);
        const int asmem = (3 * DHn + 2 * LCH) * AST * (int)sizeof(float);  // 87,040
        cudaFuncSetAttribute(attn_out_kernel,
                             cudaFuncAttributeMaxDynamicSharedMemorySize, asmem);
        attn_out_kernel<<<gkv, 256, asmem>>>(qkv_p, s_p, ahl_p);
    }

    // GEMM2: out = attn @ Wout^T
    {
        dim3 grid(Cn / 128, M / 128);
        gemm_hmma<<<grid, 256, gemm_smem>>>(ahl_p, wo_p, out, Cn);
    }
}